// round 14
// baseline (speedup 1.0000x reference)
#include <cuda_runtime.h>
#include <cuda_fp16.h>
#include <math.h>
#include <stdint.h>

#define NN   50000
#define NE   800000
#define D_IN 128
#define D_HID 256
#define D_OUT 128
#define NL   8

// ---------------- weight buffer layout (transposed, K-major [N][K]) ------
#define WB_L1   0                         // lin1: [256][128]
#define WB_LYR  32768                     // layers: 8 x [256][512]  (W' = beta*W + omb*I)
#define WB_L2   (32768 + 8 * 131072)      // lin2: [128][256]
#define WB_TOT  (WB_L2 + 32768)

// ------------------------- static device scratch -------------------------
__device__ float  g_dis[NN];
__device__ int    g_rowptr[NN + 1];
__device__ int    g_cnt[NN];
__device__ int    g_bsum[64];
__device__ int    g_boff[64];
__device__ int2   g_ew[NE];                          // packed (src, w-as-int)
__device__ __half g_hh[(size_t)NN * D_HID];          // fp16 h (raw GEMM out; x0 after lin1)
__device__ __half g_Af[(size_t)NN * 512];            // fp16 A: 0..255 t (or h_norm); 256..511 0.5*x0
__device__ __half g_xinf[(size_t)NN * D_IN];         // fp16 input x
__device__ __half g_Wf_hi[WB_TOT];                   // fp16 weight split
__device__ __half g_Wf_lo[WB_TOT];
__device__ double g_accA[2][2];                      // [parity][sum, sumsq]

// ------------------------- helpers -------------------------
__device__ __forceinline__ uint32_t smem_u32(const void* p) {
    uint32_t a;
    asm("{ .reg .u64 t; cvta.to.shared.u64 t, %1; cvt.u32.u64 %0, t; }" : "=r"(a) : "l"(p));
    return a;
}
__device__ __forceinline__ void cp16(uint32_t dst, const void* src) {
    asm volatile("cp.async.cg.shared.global [%0], [%1], 16;" :: "r"(dst), "l"(src));
}
#define CP_COMMIT() asm volatile("cp.async.commit_group;" ::: "memory")
#define CP_WAIT1()  asm volatile("cp.async.wait_group 1;" ::: "memory")

__device__ __forceinline__ void ldm_x4(uint32_t* r, uint32_t addr) {
    asm volatile("ldmatrix.sync.aligned.m8n8.x4.shared.b16 {%0,%1,%2,%3}, [%4];"
                 : "=r"(r[0]), "=r"(r[1]), "=r"(r[2]), "=r"(r[3]) : "r"(addr));
}
__device__ __forceinline__ void mma16816h(float* c, const uint32_t* a, const uint32_t* b) {
    asm volatile("mma.sync.aligned.m16n8k16.row.col.f32.f16.f16.f32 "
                 "{%0,%1,%2,%3}, {%4,%5,%6,%7}, {%8,%9}, {%0,%1,%2,%3};"
                 : "+f"(c[0]), "+f"(c[1]), "+f"(c[2]), "+f"(c[3])
                 : "r"(a[0]), "r"(a[1]), "r"(a[2]), "r"(a[3]), "r"(b[0]), "r"(b[1]));
}
__device__ __forceinline__ void split2h(float v, __half& h, __half& l) {
    h = __float2half_rn(v);
    l = __float2half_rn(v - __half2float(h));
}

// ------------------------- setup kernels -------------------------
__global__ void k_zero() {
    int i = blockIdx.x * blockDim.x + threadIdx.x;
    if (i < NN) g_cnt[i] = 0;
}
__global__ void k_count(const int* __restrict__ ei) {
    int e = blockIdx.x * blockDim.x + threadIdx.x;
    if (e < NE) atomicAdd(&g_cnt[ei[NE + e]], 1);
}
__device__ __forceinline__ int block_scan_inc(int v, int* wsum) {
    int lane = threadIdx.x & 31, wid = threadIdx.x >> 5;
#pragma unroll
    for (int o = 1; o < 32; o <<= 1) { int t = __shfl_up_sync(~0u, v, o); if (lane >= o) v += t; }
    if (lane == 31) wsum[wid] = v;
    __syncthreads();
    if (wid == 0) {
        int w = wsum[lane];
#pragma unroll
        for (int o = 1; o < 32; o <<= 1) { int t = __shfl_up_sync(~0u, w, o); if (lane >= o) w += t; }
        wsum[lane] = w;
    }
    __syncthreads();
    return v + (wid > 0 ? wsum[wid - 1] : 0);
}
__global__ void k_scan_part() {
    __shared__ int wsum[32];
    int i = blockIdx.x * 1024 + threadIdx.x;
    int v = (i < NN) ? g_cnt[i] : 0;
    int inc = block_scan_inc(v, wsum);
    if (threadIdx.x == 1023) g_bsum[blockIdx.x] = inc;
}
__global__ void k_scan_top() {
    int lane = threadIdx.x;
    int v0 = (lane < 49) ? g_bsum[lane] : 0;
    int v1 = (lane + 32 < 49) ? g_bsum[lane + 32] : 0;
    int s0 = v0;
#pragma unroll
    for (int o = 1; o < 32; o <<= 1) { int t = __shfl_up_sync(~0u, s0, o); if (lane >= o) s0 += t; }
    int tot0 = __shfl_sync(~0u, s0, 31);
    int s1 = v1;
#pragma unroll
    for (int o = 1; o < 32; o <<= 1) { int t = __shfl_up_sync(~0u, s1, o); if (lane >= o) s1 += t; }
    int tot1 = __shfl_sync(~0u, s1, 31);
    g_boff[lane] = s0 - v0;
    if (lane + 32 < 49) g_boff[lane + 32] = tot0 + s1 - v1;
    if (lane == 0) g_rowptr[NN] = tot0 + tot1;
}
__global__ void k_scan_out() {
    __shared__ int wsum[32];
    int i = blockIdx.x * 1024 + threadIdx.x;
    int v = (i < NN) ? g_cnt[i] : 0;
    int inc = block_scan_inc(v, wsum);
    if (i < NN) {
        int rp = g_boff[blockIdx.x] + inc - v;
        g_rowptr[i] = rp;
        g_cnt[i] = rp;
        g_dis[i] = rsqrtf((float)(v + 1));
    }
}
__global__ void k_scatter(const int* __restrict__ ei) {
    int e = blockIdx.x * blockDim.x + threadIdx.x;
    if (e < NE) {
        int r = ei[e];
        int c = ei[NE + e];
        int s = atomicAdd(&g_cnt[c], 1);
        g_ew[s] = make_int2(r, __float_as_int(g_dis[r] * g_dis[c]));
    }
}

// ------------------------- fused weight + input prep (fp16) --------------
__global__ void k_prep_wx(const float* __restrict__ lin1_w, const float* __restrict__ w1,
                          const float* __restrict__ w2, const float* __restrict__ lin2_w,
                          const float* __restrict__ x) {
    int idx = blockIdx.x * blockDim.x + threadIdx.x;
    if (idx < WB_TOT) {
        float v;
        if (idx < WB_LYR) {
            int n = idx >> 7, k = idx & 127;
            v = lin1_w[k * 256 + n];
        } else if (idx < WB_L2) {
            int r = idx - WB_LYR;
            int l = r >> 17;
            int q = r & 131071;
            int n = q >> 9, k = q & 511;
            float beta = logf((float)(l + 2) / (float)(l + 1));
            float omb = 1.0f - beta;
            if (k < 256) v = beta * w1[l * 65536 + k * 256 + n] + ((k == n) ? omb : 0.0f);
            else {
                int k2 = k - 256;
                v = beta * w2[l * 65536 + k2 * 256 + n] + ((k2 == n) ? omb : 0.0f);
            }
        } else {
            int r = idx - WB_L2;
            int n = r >> 8, k = r & 255;
            v = lin2_w[k * 128 + n];
        }
        __half h, l;
        split2h(v, h, l);
        g_Wf_hi[idx] = h;
        g_Wf_lo[idx] = l;
    } else {
        size_t xi = (size_t)idx - WB_TOT;
        if (xi < (size_t)NN * D_IN) g_xinf[xi] = __float2half_rn(x[xi]);
    }
}

// ------------------------- SpMM (warp-cooperative edge fetch) ------------
// One coalesced int2 load serves up to 32 edges (shfl broadcast); vector
// gathers form an independent stream (unroll 8). lane owns 8 cols.
__global__ void __launch_bounds__(64, 24) k_spmm(int l, const float* __restrict__ gam,
                                                 const float* __restrict__ bet) {
    int par = l & 1;
    if (blockIdx.x == 0 && threadIdx.x == 0) { g_accA[par][0] = 0.0; g_accA[par][1] = 0.0; }
    int warp = blockIdx.x * 2 + (threadIdx.x >> 5);
    int lane = threadIdx.x & 31;
    if (warp >= NN) return;

    float ca[8], cb[8];
    if (l == 0) {
#pragma unroll
        for (int j = 0; j < 8; j++) { ca[j] = 1.0f; cb[j] = 0.0f; }
    } else {
        int pp = (l - 1) & 1;
        double cnt = (double)NN * (double)D_HID;
        double mu = g_accA[pp][0] / cnt;
        double var = g_accA[pp][1] / cnt - mu * mu;
        if (var < 0.0) var = 0.0;
        float inv = (float)(1.0 / (sqrt(var) + 1e-5));
        float muf = (float)mu;
        int c0 = lane * 8;
        float4 ga = *(const float4*)(gam + c0);
        float4 gb = *(const float4*)(gam + c0 + 4);
        float4 ba = *(const float4*)(bet + c0);
        float4 bb = *(const float4*)(bet + c0 + 4);
        float gv[8] = {ga.x, ga.y, ga.z, ga.w, gb.x, gb.y, gb.z, gb.w};
        float bv[8] = {ba.x, ba.y, ba.z, ba.w, bb.x, bb.y, bb.z, bb.w};
#pragma unroll
        for (int j = 0; j < 8; j++) { ca[j] = gv[j] * inv; cb[j] = bv[j] - muf * ca[j]; }
    }

    int c = warp;
    float dc = g_dis[c];
    float wself = dc * dc;
    float acc[8];
    {
        uint4 q = __ldg((const uint4*)(g_hh + (size_t)c * D_HID + lane * 8));
        float2 f0 = __half22float2(*(__half2*)&q.x);
        float2 f1 = __half22float2(*(__half2*)&q.y);
        float2 f2 = __half22float2(*(__half2*)&q.z);
        float2 f3 = __half22float2(*(__half2*)&q.w);
        float v[8] = {f0.x, f0.y, f1.x, f1.y, f2.x, f2.y, f3.x, f3.y};
#pragma unroll
        for (int j = 0; j < 8; j++) acc[j] = wself * fmaxf(ca[j] * v[j] + cb[j], 0.0f);
    }

    int beg = g_rowptr[c], end = g_rowptr[c + 1];
    for (int base = beg; base < end; base += 32) {
        int n = end - base; if (n > 32) n = 32;
        int2 ewl = make_int2(0, 0);
        if (base + lane < end) ewl = __ldg(&g_ew[base + lane]);
#pragma unroll 8
        for (int j = 0; j < n; j++) {
            int   s = __shfl_sync(~0u, ewl.x, j);
            float w = __int_as_float(__shfl_sync(~0u, ewl.y, j));
            uint4 q = __ldg((const uint4*)(g_hh + (size_t)s * D_HID + lane * 8));
            float2 f0 = __half22float2(*(__half2*)&q.x);
            float2 f1 = __half22float2(*(__half2*)&q.y);
            float2 f2 = __half22float2(*(__half2*)&q.z);
            float2 f3 = __half22float2(*(__half2*)&q.w);
            float v[8] = {f0.x, f0.y, f1.x, f1.y, f2.x, f2.y, f3.x, f3.y};
#pragma unroll
            for (int k = 0; k < 8; k++) acc[k] += w * fmaxf(ca[k] * v[k] + cb[k], 0.0f);
        }
    }

    __half2 o[4];
#pragma unroll
    for (int j = 0; j < 4; j++)
        o[j] = __floats2half2_rn(0.5f * acc[2 * j], 0.5f * acc[2 * j + 1]);
    *(uint4*)(g_Af + (size_t)c * 512 + lane * 8) = *(uint4*)o;
}

// ------------------------- fp16 2-pass GEMM (8 warps, 2-stage, 2 CTA/SM) -
// stage: A fp16 (10240B) | B_hi (10240B) | B_lo (10240B)
// mode 1: lin1   A=g_xinf (lda=128), K=128 : relu(acc+bias)->g_hh + 0.5x0 fp16
// mode 2: layer  A=g_Af   (lda=512), K=512 : acc -> g_hh + fp32 stats
// mode 3: lin2   A=g_Af   (lda=512), K=256 : relu(acc+bias)->Cout
#define STG_SZ 30720
#define SM_TOTAL (2 * STG_SZ)

__global__ void __launch_bounds__(256, 2) k_mma(int mode, int bOff, int K, int ldb, int N,
                                                const float* __restrict__ bias,
                                                float* __restrict__ Cout, int parity) {
    extern __shared__ char smem[];
    uint32_t sb = smem_u32(smem);
    int tid = threadIdx.x;
    int lane = tid & 31, wrp = tid >> 5;
    int wm = wrp & 1, wn = wrp >> 1;
    int m0 = blockIdx.y * 128, n0 = blockIdx.x * 128;

    const __half* A = (mode == 1) ? g_xinf : g_Af;
    const int lda = (mode == 1) ? 128 : 512;
    const __half* Bhi = g_Wf_hi + bOff;
    const __half* Blo = g_Wf_lo + bOff;

    const int nch = K / 32;

    int r0i = tid >> 2, seg0 = (tid & 3);
    int r1i = (tid + 256) >> 2;

    auto load_stage = [&](int s, int ch) {
        int kb = ch * 32;
        uint32_t base = sb + s * STG_SZ;
        int gr0 = m0 + r0i; if (gr0 >= NN) gr0 = 0;
        int gr1 = m0 + r1i; if (gr1 >= NN) gr1 = 0;
        uint32_t d0 = base + r0i * 80 + seg0 * 16;
        uint32_t d1 = base + r1i * 80 + seg0 * 16;
        cp16(d0, A + (size_t)gr0 * lda + kb + seg0 * 8);
        cp16(d1, A + (size_t)gr1 * lda + kb + seg0 * 8);
        const __half* b0h = Bhi + (size_t)(n0 + r0i) * ldb + kb + seg0 * 8;
        const __half* b1h = Bhi + (size_t)(n0 + r1i) * ldb + kb + seg0 * 8;
        const __half* b0l = Blo + (size_t)(n0 + r0i) * ldb + kb + seg0 * 8;
        const __half* b1l = Blo + (size_t)(n0 + r1i) * ldb + kb + seg0 * 8;
        cp16(d0 + 10240, b0h);  cp16(d1 + 10240, b1h);
        cp16(d0 + 20480, b0l);  cp16(d1 + 20480, b1l);
    };

    float acc[4][4][4];
#pragma unroll
    for (int i = 0; i < 4; i++)
#pragma unroll
        for (int j = 0; j < 4; j++)
#pragma unroll
            for (int p = 0; p < 4; p++) acc[i][j][p] = 0.0f;

    load_stage(0, 0); CP_COMMIT();
    load_stage(1, 1); CP_COMMIT();

    int a_row = wm * 64 + (lane & 7) + ((lane >> 3) & 1) * 8;
    int a_colh = (lane >> 4) * 8;
    int b_row2 = wn * 32 + ((lane >> 4) & 1) * 8 + (lane & 7);
    int b_colh = ((lane >> 3) & 1) * 8;

    for (int ch = 0; ch < nch; ch++) {
        int st = ch & 1;
        CP_WAIT1();
        __syncthreads();
        uint32_t base = sb + st * STG_SZ;
#pragma unroll
        for (int k16 = 0; k16 < 2; k16++) {
            uint32_t ah[4][4], bh[4][2], bl[4][2];
#pragma unroll
            for (int mt = 0; mt < 4; mt++) {
                uint32_t ad = base + (a_row + mt * 16) * 80 + (k16 * 16 + a_colh) * 2;
                ldm_x4(ah[mt], ad);
            }
#pragma unroll
            for (int np = 0; np < 2; np++) {
                uint32_t bd = base + 10240 + (b_row2 + np * 16) * 80 + (k16 * 16 + b_colh) * 2;
                uint32_t r4[4];
                ldm_x4(r4, bd);
                bh[np * 2][0] = r4[0]; bh[np * 2][1] = r4[1];
                bh[np * 2 + 1][0] = r4[2]; bh[np * 2 + 1][1] = r4[3];
                ldm_x4(r4, bd + 10240);
                bl[np * 2][0] = r4[0]; bl[np * 2][1] = r4[1];
                bl[np * 2 + 1][0] = r4[2]; bl[np * 2 + 1][1] = r4[3];
            }
#pragma unroll
            for (int mt = 0; mt < 4; mt++)
#pragma unroll
                for (int nt = 0; nt < 4; nt++) {
                    mma16816h(acc[mt][nt], ah[mt], bh[nt]);
                    mma16816h(acc[mt][nt], ah[mt], bl[nt]);
                }
        }
        __syncthreads();
        if (ch + 2 < nch) load_stage(st, ch + 2);
        CP_COMMIT();
    }

    // ------------- epilogue -------------
    float sum = 0.0f, ssum = 0.0f;
    int rbase = m0 + wm * 64 + (lane >> 2);
    int cbase = n0 + wn * 32 + (lane & 3) * 2;
#pragma unroll
    for (int mt = 0; mt < 4; mt++) {
#pragma unroll
        for (int half = 0; half < 2; half++) {
            int row = rbase + mt * 16 + half * 8;
            if (row >= NN) continue;
#pragma unroll
            for (int nt = 0; nt < 4; nt++) {
                int c = cbase + nt * 8;
                float v0 = acc[mt][nt][half * 2 + 0];
                float v1 = acc[mt][nt][half * 2 + 1];
                if (mode == 2) {
                    *(__half2*)(g_hh + (size_t)row * 256 + c) = __floats2half2_rn(v0, v1);
                    sum += v0 + v1;
                    ssum += v0 * v0 + v1 * v1;
                } else if (mode == 1) {
                    float r0 = fmaxf(v0 + __ldg(&bias[c]), 0.0f);
                    float r1 = fmaxf(v1 + __ldg(&bias[c + 1]), 0.0f);
                    *(__half2*)(g_hh + (size_t)row * 256 + c) = __floats2half2_rn(r0, r1);
                    *(__half2*)(g_Af + (size_t)row * 512 + 256 + c) =
                        __floats2half2_rn(0.5f * r0, 0.5f * r1);
                } else {
                    float r0 = fmaxf(v0 + __ldg(&bias[c]), 0.0f);
                    float r1 = fmaxf(v1 + __ldg(&bias[c + 1]), 0.0f);
                    *(float2*)(Cout + (size_t)row * N + c) = make_float2(r0, r1);
                }
            }
        }
    }
    if (mode == 2) {
#pragma unroll
        for (int off = 16; off > 0; off >>= 1) {
            sum  += __shfl_down_sync(0xffffffffu, sum, off);
            ssum += __shfl_down_sync(0xffffffffu, ssum, off);
        }
        __syncthreads();
        float* rs  = (float*)smem;
        float* rss = (float*)smem + 32;
        if (lane == 0) { rs[wrp] = sum; rss[wrp] = ssum; }
        __syncthreads();
        if (tid == 0) {
            float S = 0.f, SS = 0.f;
            for (int w = 0; w < 8; w++) { S += rs[w]; SS += rss[w]; }
            atomicAdd(&g_accA[parity][0], (double)S);
            atomicAdd(&g_accA[parity][1], (double)SS);
        }
    }
}

// ------------------------- final norm -> lin2 input (fp16) ---------------
__global__ void k_norm_final(const float* __restrict__ gam, const float* __restrict__ bet) {
    double cnt = (double)NN * (double)D_HID;
    double mu = g_accA[1][0] / cnt;
    double var = g_accA[1][1] / cnt - mu * mu;
    if (var < 0.0) var = 0.0;
    float inv = (float)(1.0 / (sqrt(var) + 1e-5));
    float muf = (float)mu;
    size_t total = (size_t)NN * D_HID / 4;
    size_t i = (size_t)blockIdx.x * blockDim.x + threadIdx.x;
    if (i >= total) return;
    uint2 q = *(const uint2*)(g_hh + i * 4);
    float2 f0 = __half22float2(*(__half2*)&q.x);
    float2 f1 = __half22float2(*(__half2*)&q.y);
    int c = (int)((i * 4) & (D_HID - 1));
    float4 gg = *(const float4*)(gam + c);
    float4 bb = *(const float4*)(bet + c);
    float r0 = fmaxf(gg.x * ((f0.x - muf) * inv) + bb.x, 0.0f);
    float r1 = fmaxf(gg.y * ((f0.y - muf) * inv) + bb.y, 0.0f);
    float r2 = fmaxf(gg.z * ((f1.x - muf) * inv) + bb.z, 0.0f);
    float r3 = fmaxf(gg.w * ((f1.y - muf) * inv) + bb.w, 0.0f);
    size_t row = (i * 4) >> 8;
    size_t base = row * 512 + c;
    *(__half2*)(g_Af + base)     = __floats2half2_rn(r0, r1);
    *(__half2*)(g_Af + base + 2) = __floats2half2_rn(r2, r3);
}

// ------------------------- launch -------------------------
extern "C" void kernel_launch(void* const* d_in, const int* in_sizes, int n_in,
                              void* d_out, int out_size) {
    const float* x       = (const float*)d_in[0];
    const int*   ei      = (const int*)  d_in[1];
    const float* lin1_w  = (const float*)d_in[2];
    const float* lin1_b  = (const float*)d_in[3];
    const float* conv_w1 = (const float*)d_in[4];
    const float* conv_w2 = (const float*)d_in[5];
    const float* gamma   = (const float*)d_in[6];
    const float* betaa   = (const float*)d_in[7];
    const float* lin2_w  = (const float*)d_in[8];
    const float* lin2_b  = (const float*)d_in[9];
    float* out = (float*)d_out;

    static int smem_set = 0;
    if (!smem_set) {
        cudaFuncSetAttribute(k_mma, cudaFuncAttributeMaxDynamicSharedMemorySize, SM_TOTAL);
        smem_set = 1;
    }

    const int MT = (NN + 127) / 128;  // 391
    const int PREP_N = WB_TOT + NN * D_IN;

    k_prep_wx<<<(PREP_N + 255) / 256, 256>>>(lin1_w, conv_w1, conv_w2, lin2_w, x);
    k_zero<<<(NN + 255) / 256, 256>>>();
    k_count<<<(NE + 255) / 256, 256>>>(ei);
    k_mma<<<dim3(2, MT), 256, SM_TOTAL>>>(1, WB_L1, 128, 128, 256, lin1_b, nullptr, 0);
    k_scan_part<<<49, 1024>>>();
    k_scan_top<<<1, 32>>>();
    k_scan_out<<<49, 1024>>>();
    k_scatter<<<(NE + 255) / 256, 256>>>(ei);

    for (int l = 0; l < NL; l++) {
        k_spmm<<<(NN + 1) / 2, 64>>>(l, gamma + (size_t)(l > 0 ? l - 1 : 0) * D_HID,
                                     betaa + (size_t)(l > 0 ? l - 1 : 0) * D_HID);
        k_mma<<<dim3(2, MT), 256, SM_TOTAL>>>(2, WB_LYR + l * 131072, 512, 512, 256,
                                              nullptr, nullptr, l & 1);
    }

    k_norm_final<<<(NN * D_HID / 4 + 255) / 256, 256>>>(gamma + 7 * (size_t)D_HID,
                                                        betaa + 7 * (size_t)D_HID);

    k_mma<<<dim3(1, MT), 256, SM_TOTAL>>>(3, WB_L2, 256, 256, 128, lin2_b, out, 0);

    (void)in_sizes; (void)n_in; (void)out_size;
}

// round 15
// speedup vs baseline: 1.0252x; 1.0252x over previous
#include <cuda_runtime.h>
#include <cuda_fp16.h>
#include <math.h>
#include <stdint.h>

#define NN   50000
#define NE   800000
#define D_IN 128
#define D_HID 256
#define D_OUT 128
#define NL   8

// ---------------- weight buffer layout (transposed, K-major [N][K]) ------
#define WB_L1   0                         // lin1: [256][128]
#define WB_LYR  32768                     // layers: 8 x [256][512]  (W' = beta*W + omb*I)
#define WB_L2   (32768 + 8 * 131072)      // lin2: [128][256]
#define WB_TOT  (WB_L2 + 32768)

// ------------------------- static device scratch -------------------------
__device__ float  g_dis[NN];
__device__ int    g_rowptr[NN + 1];
__device__ int    g_cnt[NN];
__device__ int    g_bsum[64];
__device__ int    g_boff[64];
__device__ int2   g_ew[NE];                          // packed (src, w-as-int)
__device__ __half g_hh[(size_t)NN * D_HID];          // fp16 h (raw GEMM out; x0 after lin1)
__device__ __half g_Af[(size_t)NN * 512];            // fp16 A: 0..255 t (or h_norm); 256..511 0.5*x0
__device__ __half g_xinf[(size_t)NN * D_IN];         // fp16 input x
__device__ __half g_Wf_hi[WB_TOT];                   // fp16 weight split
__device__ __half g_Wf_lo[WB_TOT];
__device__ double g_accA[2][2];                      // [parity][sum, sumsq]

// ------------------------- helpers -------------------------
__device__ __forceinline__ uint32_t smem_u32(const void* p) {
    uint32_t a;
    asm("{ .reg .u64 t; cvta.to.shared.u64 t, %1; cvt.u32.u64 %0, t; }" : "=r"(a) : "l"(p));
    return a;
}
__device__ __forceinline__ void cp16(uint32_t dst, const void* src) {
    asm volatile("cp.async.cg.shared.global [%0], [%1], 16;" :: "r"(dst), "l"(src));
}
#define CP_COMMIT() asm volatile("cp.async.commit_group;" ::: "memory")
#define CP_WAIT2()  asm volatile("cp.async.wait_group 2;" ::: "memory")

__device__ __forceinline__ void ldm_x4(uint32_t* r, uint32_t addr) {
    asm volatile("ldmatrix.sync.aligned.m8n8.x4.shared.b16 {%0,%1,%2,%3}, [%4];"
                 : "=r"(r[0]), "=r"(r[1]), "=r"(r[2]), "=r"(r[3]) : "r"(addr));
}
__device__ __forceinline__ void mma16816h(float* c, const uint32_t* a, const uint32_t* b) {
    asm volatile("mma.sync.aligned.m16n8k16.row.col.f32.f16.f16.f32 "
                 "{%0,%1,%2,%3}, {%4,%5,%6,%7}, {%8,%9}, {%0,%1,%2,%3};"
                 : "+f"(c[0]), "+f"(c[1]), "+f"(c[2]), "+f"(c[3])
                 : "r"(a[0]), "r"(a[1]), "r"(a[2]), "r"(a[3]), "r"(b[0]), "r"(b[1]));
}
__device__ __forceinline__ void split2h(float v, __half& h, __half& l) {
    h = __float2half_rn(v);
    l = __float2half_rn(v - __half2float(h));
}

// ------------------------- setup kernels -------------------------
__global__ void k_zero() {
    int i = blockIdx.x * blockDim.x + threadIdx.x;
    if (i < NN) g_cnt[i] = 0;
}
__global__ void k_count(const int* __restrict__ ei) {
    int e = blockIdx.x * blockDim.x + threadIdx.x;
    if (e < NE) atomicAdd(&g_cnt[ei[NE + e]], 1);
}
__device__ __forceinline__ int block_scan_inc(int v, int* wsum) {
    int lane = threadIdx.x & 31, wid = threadIdx.x >> 5;
#pragma unroll
    for (int o = 1; o < 32; o <<= 1) { int t = __shfl_up_sync(~0u, v, o); if (lane >= o) v += t; }
    if (lane == 31) wsum[wid] = v;
    __syncthreads();
    if (wid == 0) {
        int w = wsum[lane];
#pragma unroll
        for (int o = 1; o < 32; o <<= 1) { int t = __shfl_up_sync(~0u, w, o); if (lane >= o) w += t; }
        wsum[lane] = w;
    }
    __syncthreads();
    return v + (wid > 0 ? wsum[wid - 1] : 0);
}
__global__ void k_scan_part() {
    __shared__ int wsum[32];
    int i = blockIdx.x * 1024 + threadIdx.x;
    int v = (i < NN) ? g_cnt[i] : 0;
    int inc = block_scan_inc(v, wsum);
    if (threadIdx.x == 1023) g_bsum[blockIdx.x] = inc;
}
__global__ void k_scan_top() {
    int lane = threadIdx.x;
    int v0 = (lane < 49) ? g_bsum[lane] : 0;
    int v1 = (lane + 32 < 49) ? g_bsum[lane + 32] : 0;
    int s0 = v0;
#pragma unroll
    for (int o = 1; o < 32; o <<= 1) { int t = __shfl_up_sync(~0u, s0, o); if (lane >= o) s0 += t; }
    int tot0 = __shfl_sync(~0u, s0, 31);
    int s1 = v1;
#pragma unroll
    for (int o = 1; o < 32; o <<= 1) { int t = __shfl_up_sync(~0u, s1, o); if (lane >= o) s1 += t; }
    int tot1 = __shfl_sync(~0u, s1, 31);
    g_boff[lane] = s0 - v0;
    if (lane + 32 < 49) g_boff[lane + 32] = tot0 + s1 - v1;
    if (lane == 0) g_rowptr[NN] = tot0 + tot1;
}
__global__ void k_scan_out() {
    __shared__ int wsum[32];
    int i = blockIdx.x * 1024 + threadIdx.x;
    int v = (i < NN) ? g_cnt[i] : 0;
    int inc = block_scan_inc(v, wsum);
    if (i < NN) {
        int rp = g_boff[blockIdx.x] + inc - v;
        g_rowptr[i] = rp;
        g_cnt[i] = rp;
        g_dis[i] = rsqrtf((float)(v + 1));
    }
}
__global__ void k_scatter(const int* __restrict__ ei) {
    int e = blockIdx.x * blockDim.x + threadIdx.x;
    if (e < NE) {
        int r = ei[e];
        int c = ei[NE + e];
        int s = atomicAdd(&g_cnt[c], 1);
        g_ew[s] = make_int2(r, __float_as_int(g_dis[r] * g_dis[c]));
    }
}

// ------------------------- fused weight + input prep (fp16) --------------
__global__ void k_prep_wx(const float* __restrict__ lin1_w, const float* __restrict__ w1,
                          const float* __restrict__ w2, const float* __restrict__ lin2_w,
                          const float* __restrict__ x) {
    int idx = blockIdx.x * blockDim.x + threadIdx.x;
    if (idx < WB_TOT) {
        float v;
        if (idx < WB_LYR) {
            int n = idx >> 7, k = idx & 127;
            v = lin1_w[k * 256 + n];
        } else if (idx < WB_L2) {
            int r = idx - WB_LYR;
            int l = r >> 17;
            int q = r & 131071;
            int n = q >> 9, k = q & 511;
            float beta = logf((float)(l + 2) / (float)(l + 1));
            float omb = 1.0f - beta;
            if (k < 256) v = beta * w1[l * 65536 + k * 256 + n] + ((k == n) ? omb : 0.0f);
            else {
                int k2 = k - 256;
                v = beta * w2[l * 65536 + k2 * 256 + n] + ((k2 == n) ? omb : 0.0f);
            }
        } else {
            int r = idx - WB_L2;
            int n = r >> 8, k = r & 255;
            v = lin2_w[k * 128 + n];
        }
        __half h, l;
        split2h(v, h, l);
        g_Wf_hi[idx] = h;
        g_Wf_lo[idx] = l;
    } else {
        size_t xi = (size_t)idx - WB_TOT;
        if (xi < (size_t)NN * D_IN) g_xinf[xi] = __float2half_rn(x[xi]);
    }
}

// ------------------------- SpMM (fp16 gather, fused norm+relu) -----------
// R13 form (proven ~best): per-warp node, unroll-4, int2 edges, 8 cols/lane.
__global__ void __launch_bounds__(64, 24) k_spmm(int l, const float* __restrict__ gam,
                                                 const float* __restrict__ bet) {
    int par = l & 1;
    if (blockIdx.x == 0 && threadIdx.x == 0) { g_accA[par][0] = 0.0; g_accA[par][1] = 0.0; }
    int warp = blockIdx.x * 2 + (threadIdx.x >> 5);
    int lane = threadIdx.x & 31;
    if (warp >= NN) return;

    float ca[8], cb[8];
    if (l == 0) {
#pragma unroll
        for (int j = 0; j < 8; j++) { ca[j] = 1.0f; cb[j] = 0.0f; }
    } else {
        int pp = (l - 1) & 1;
        double cnt = (double)NN * (double)D_HID;
        double mu = g_accA[pp][0] / cnt;
        double var = g_accA[pp][1] / cnt - mu * mu;
        if (var < 0.0) var = 0.0;
        float inv = (float)(1.0 / (sqrt(var) + 1e-5));
        float muf = (float)mu;
        int c0 = lane * 8;
        float4 ga = *(const float4*)(gam + c0);
        float4 gb = *(const float4*)(gam + c0 + 4);
        float4 ba = *(const float4*)(bet + c0);
        float4 bb = *(const float4*)(bet + c0 + 4);
        float gv[8] = {ga.x, ga.y, ga.z, ga.w, gb.x, gb.y, gb.z, gb.w};
        float bv[8] = {ba.x, ba.y, ba.z, ba.w, bb.x, bb.y, bb.z, bb.w};
#pragma unroll
        for (int j = 0; j < 8; j++) { ca[j] = gv[j] * inv; cb[j] = bv[j] - muf * ca[j]; }
    }

    int c = warp;
    float dc = g_dis[c];
    float wself = dc * dc;
    float acc[8];
    {
        uint4 q = __ldg((const uint4*)(g_hh + (size_t)c * D_HID + lane * 8));
        float2 f0 = __half22float2(*(__half2*)&q.x);
        float2 f1 = __half22float2(*(__half2*)&q.y);
        float2 f2 = __half22float2(*(__half2*)&q.z);
        float2 f3 = __half22float2(*(__half2*)&q.w);
        float v[8] = {f0.x, f0.y, f1.x, f1.y, f2.x, f2.y, f3.x, f3.y};
#pragma unroll
        for (int j = 0; j < 8; j++) acc[j] = wself * fmaxf(ca[j] * v[j] + cb[j], 0.0f);
    }

    int beg = g_rowptr[c], end = g_rowptr[c + 1];
#pragma unroll 4
    for (int e = beg; e < end; e++) {
        int2 ew = __ldg(&g_ew[e]);
        int   s = ew.x;
        float w = __int_as_float(ew.y);
        uint4 q = __ldg((const uint4*)(g_hh + (size_t)s * D_HID + lane * 8));
        float2 f0 = __half22float2(*(__half2*)&q.x);
        float2 f1 = __half22float2(*(__half2*)&q.y);
        float2 f2 = __half22float2(*(__half2*)&q.z);
        float2 f3 = __half22float2(*(__half2*)&q.w);
        float v[8] = {f0.x, f0.y, f1.x, f1.y, f2.x, f2.y, f3.x, f3.y};
#pragma unroll
        for (int j = 0; j < 8; j++) acc[j] += w * fmaxf(ca[j] * v[j] + cb[j], 0.0f);
    }

    __half2 o[4];
#pragma unroll
    for (int j = 0; j < 4; j++)
        o[j] = __floats2half2_rn(0.5f * acc[2 * j], 0.5f * acc[2 * j + 1]);
    *(uint4*)(g_Af + (size_t)c * 512 + lane * 8) = *(uint4*)o;
}

// ------------------------- fp16 2-pass GEMM (3-stage, wait_group 2) ------
// stage: A fp16 (10240B) | B_hi (10240B) | B_lo (10240B); 3 stages, 2 CTA/SM
// mode 1: lin1   A=g_xinf (lda=128), K=128 : relu(acc+bias)->g_hh + 0.5x0 fp16
// mode 2: layer  A=g_Af   (lda=512), K=512 : acc -> g_hh + fp32 stats
// mode 3: lin2   A=g_Af   (lda=512), K=256 : relu(acc+bias)->Cout
#define STG_SZ 30720
#define NSTG 3
#define SM_TOTAL (NSTG * STG_SZ)

__global__ void __launch_bounds__(256, 2) k_mma(int mode, int bOff, int K, int ldb, int N,
                                                const float* __restrict__ bias,
                                                float* __restrict__ Cout, int parity) {
    extern __shared__ char smem[];
    uint32_t sb = smem_u32(smem);
    int tid = threadIdx.x;
    int lane = tid & 31, wrp = tid >> 5;
    int wm = wrp & 1, wn = wrp >> 1;
    int m0 = blockIdx.y * 128, n0 = blockIdx.x * 128;

    const __half* A = (mode == 1) ? g_xinf : g_Af;
    const int lda = (mode == 1) ? 128 : 512;
    const __half* Bhi = g_Wf_hi + bOff;
    const __half* Blo = g_Wf_lo + bOff;

    const int nch = K / 32;

    int r0i = tid >> 2, seg0 = (tid & 3);
    int r1i = (tid + 256) >> 2;

    auto load_stage = [&](int s, int ch) {
        int kb = ch * 32;
        uint32_t base = sb + s * STG_SZ;
        int gr0 = m0 + r0i; if (gr0 >= NN) gr0 = 0;
        int gr1 = m0 + r1i; if (gr1 >= NN) gr1 = 0;
        uint32_t d0 = base + r0i * 80 + seg0 * 16;
        uint32_t d1 = base + r1i * 80 + seg0 * 16;
        cp16(d0, A + (size_t)gr0 * lda + kb + seg0 * 8);
        cp16(d1, A + (size_t)gr1 * lda + kb + seg0 * 8);
        const __half* b0h = Bhi + (size_t)(n0 + r0i) * ldb + kb + seg0 * 8;
        const __half* b1h = Bhi + (size_t)(n0 + r1i) * ldb + kb + seg0 * 8;
        const __half* b0l = Blo + (size_t)(n0 + r0i) * ldb + kb + seg0 * 8;
        const __half* b1l = Blo + (size_t)(n0 + r1i) * ldb + kb + seg0 * 8;
        cp16(d0 + 10240, b0h);  cp16(d1 + 10240, b1h);
        cp16(d0 + 20480, b0l);  cp16(d1 + 20480, b1l);
    };

    float acc[4][4][4];
#pragma unroll
    for (int i = 0; i < 4; i++)
#pragma unroll
        for (int j = 0; j < 4; j++)
#pragma unroll
            for (int p = 0; p < 4; p++) acc[i][j][p] = 0.0f;

    load_stage(0, 0); CP_COMMIT();
    if (nch > 1) load_stage(1, 1);
    CP_COMMIT();
    if (nch > 2) load_stage(2, 2);
    CP_COMMIT();

    int a_row = wm * 64 + (lane & 7) + ((lane >> 3) & 1) * 8;
    int a_colh = (lane >> 4) * 8;
    int b_row2 = wn * 32 + ((lane >> 4) & 1) * 8 + (lane & 7);
    int b_colh = ((lane >> 3) & 1) * 8;

    for (int ch = 0; ch < nch; ch++) {
        int st = ch % NSTG;
        CP_WAIT2();
        __syncthreads();
        uint32_t base = sb + st * STG_SZ;
#pragma unroll
        for (int k16 = 0; k16 < 2; k16++) {
            uint32_t ah[4][4], bh[4][2], bl[4][2];
#pragma unroll
            for (int mt = 0; mt < 4; mt++) {
                uint32_t ad = base + (a_row + mt * 16) * 80 + (k16 * 16 + a_colh) * 2;
                ldm_x4(ah[mt], ad);
            }
#pragma unroll
            for (int np = 0; np < 2; np++) {
                uint32_t bd = base + 10240 + (b_row2 + np * 16) * 80 + (k16 * 16 + b_colh) * 2;
                uint32_t r4[4];
                ldm_x4(r4, bd);
                bh[np * 2][0] = r4[0]; bh[np * 2][1] = r4[1];
                bh[np * 2 + 1][0] = r4[2]; bh[np * 2 + 1][1] = r4[3];
                ldm_x4(r4, bd + 10240);
                bl[np * 2][0] = r4[0]; bl[np * 2][1] = r4[1];
                bl[np * 2 + 1][0] = r4[2]; bl[np * 2 + 1][1] = r4[3];
            }
#pragma unroll
            for (int mt = 0; mt < 4; mt++)
#pragma unroll
                for (int nt = 0; nt < 4; nt++) {
                    mma16816h(acc[mt][nt], ah[mt], bh[nt]);
                    mma16816h(acc[mt][nt], ah[mt], bl[nt]);
                }
        }
        __syncthreads();
        if (ch + 3 < nch) load_stage(st, ch + 3);
        CP_COMMIT();
    }

    // ------------- epilogue -------------
    float sum = 0.0f, ssum = 0.0f;
    int rbase = m0 + wm * 64 + (lane >> 2);
    int cbase = n0 + wn * 32 + (lane & 3) * 2;
#pragma unroll
    for (int mt = 0; mt < 4; mt++) {
#pragma unroll
        for (int half = 0; half < 2; half++) {
            int row = rbase + mt * 16 + half * 8;
            if (row >= NN) continue;
#pragma unroll
            for (int nt = 0; nt < 4; nt++) {
                int c = cbase + nt * 8;
                float v0 = acc[mt][nt][half * 2 + 0];
                float v1 = acc[mt][nt][half * 2 + 1];
                if (mode == 2) {
                    *(__half2*)(g_hh + (size_t)row * 256 + c) = __floats2half2_rn(v0, v1);
                    sum += v0 + v1;
                    ssum += v0 * v0 + v1 * v1;
                } else if (mode == 1) {
                    float r0 = fmaxf(v0 + __ldg(&bias[c]), 0.0f);
                    float r1 = fmaxf(v1 + __ldg(&bias[c + 1]), 0.0f);
                    *(__half2*)(g_hh + (size_t)row * 256 + c) = __floats2half2_rn(r0, r1);
                    *(__half2*)(g_Af + (size_t)row * 512 + 256 + c) =
                        __floats2half2_rn(0.5f * r0, 0.5f * r1);
                } else {
                    float r0 = fmaxf(v0 + __ldg(&bias[c]), 0.0f);
                    float r1 = fmaxf(v1 + __ldg(&bias[c + 1]), 0.0f);
                    *(float2*)(Cout + (size_t)row * N + c) = make_float2(r0, r1);
                }
            }
        }
    }
    if (mode == 2) {
#pragma unroll
        for (int off = 16; off > 0; off >>= 1) {
            sum  += __shfl_down_sync(0xffffffffu, sum, off);
            ssum += __shfl_down_sync(0xffffffffu, ssum, off);
        }
        __syncthreads();
        float* rs  = (float*)smem;
        float* rss = (float*)smem + 32;
        if (lane == 0) { rs[wrp] = sum; rss[wrp] = ssum; }
        __syncthreads();
        if (tid == 0) {
            float S = 0.f, SS = 0.f;
            for (int w = 0; w < 8; w++) { S += rs[w]; SS += rss[w]; }
            atomicAdd(&g_accA[parity][0], (double)S);
            atomicAdd(&g_accA[parity][1], (double)SS);
        }
    }
}

// ------------------------- final norm -> lin2 input (fp16) ---------------
__global__ void k_norm_final(const float* __restrict__ gam, const float* __restrict__ bet) {
    double cnt = (double)NN * (double)D_HID;
    double mu = g_accA[1][0] / cnt;
    double var = g_accA[1][1] / cnt - mu * mu;
    if (var < 0.0) var = 0.0;
    float inv = (float)(1.0 / (sqrt(var) + 1e-5));
    float muf = (float)mu;
    size_t total = (size_t)NN * D_HID / 4;
    size_t i = (size_t)blockIdx.x * blockDim.x + threadIdx.x;
    if (i >= total) return;
    uint2 q = *(const uint2*)(g_hh + i * 4);
    float2 f0 = __half22float2(*(__half2*)&q.x);
    float2 f1 = __half22float2(*(__half2*)&q.y);
    int c = (int)((i * 4) & (D_HID - 1));
    float4 gg = *(const float4*)(gam + c);
    float4 bb = *(const float4*)(bet + c);
    float r0 = fmaxf(gg.x * ((f0.x - muf) * inv) + bb.x, 0.0f);
    float r1 = fmaxf(gg.y * ((f0.y - muf) * inv) + bb.y, 0.0f);
    float r2 = fmaxf(gg.z * ((f1.x - muf) * inv) + bb.z, 0.0f);
    float r3 = fmaxf(gg.w * ((f1.y - muf) * inv) + bb.w, 0.0f);
    size_t row = (i * 4) >> 8;
    size_t base = row * 512 + c;
    *(__half2*)(g_Af + base)     = __floats2half2_rn(r0, r1);
    *(__half2*)(g_Af + base + 2) = __floats2half2_rn(r2, r3);
}

// ------------------------- launch -------------------------
extern "C" void kernel_launch(void* const* d_in, const int* in_sizes, int n_in,
                              void* d_out, int out_size) {
    const float* x       = (const float*)d_in[0];
    const int*   ei      = (const int*)  d_in[1];
    const float* lin1_w  = (const float*)d_in[2];
    const float* lin1_b  = (const float*)d_in[3];
    const float* conv_w1 = (const float*)d_in[4];
    const float* conv_w2 = (const float*)d_in[5];
    const float* gamma   = (const float*)d_in[6];
    const float* betaa   = (const float*)d_in[7];
    const float* lin2_w  = (const float*)d_in[8];
    const float* lin2_b  = (const float*)d_in[9];
    float* out = (float*)d_out;

    static int smem_set = 0;
    if (!smem_set) {
        cudaFuncSetAttribute(k_mma, cudaFuncAttributeMaxDynamicSharedMemorySize, SM_TOTAL);
        smem_set = 1;
    }

    const int MT = (NN + 127) / 128;  // 391
    const int PREP_N = WB_TOT + NN * D_IN;

    k_prep_wx<<<(PREP_N + 255) / 256, 256>>>(lin1_w, conv_w1, conv_w2, lin2_w, x);
    k_zero<<<(NN + 255) / 256, 256>>>();
    k_count<<<(NE + 255) / 256, 256>>>(ei);
    k_mma<<<dim3(2, MT), 256, SM_TOTAL>>>(1, WB_L1, 128, 128, 256, lin1_b, nullptr, 0);
    k_scan_part<<<49, 1024>>>();
    k_scan_top<<<1, 32>>>();
    k_scan_out<<<49, 1024>>>();
    k_scatter<<<(NE + 255) / 256, 256>>>(ei);

    for (int l = 0; l < NL; l++) {
        k_spmm<<<(NN + 1) / 2, 64>>>(l, gamma + (size_t)(l > 0 ? l - 1 : 0) * D_HID,
                                     betaa + (size_t)(l > 0 ? l - 1 : 0) * D_HID);
        k_mma<<<dim3(2, MT), 256, SM_TOTAL>>>(2, WB_LYR + l * 131072, 512, 512, 256,
                                              nullptr, nullptr, l & 1);
    }

    k_norm_final<<<(NN * D_HID / 4 + 255) / 256, 256>>>(gamma + 7 * (size_t)D_HID,
                                                        betaa + 7 * (size_t)D_HID);

    k_mma<<<dim3(1, MT), 256, SM_TOTAL>>>(3, WB_L2, 256, 256, 128, lin2_b, out, 0);

    (void)in_sizes; (void)n_in; (void)out_size;
}

// round 16
// speedup vs baseline: 1.2017x; 1.1722x over previous
#include <cuda_runtime.h>
#include <cuda_fp16.h>
#include <math.h>
#include <stdint.h>

#define NN   50000
#define NE   800000
#define D_IN 128
#define D_HID 256
#define D_OUT 128
#define NL   8

// ---------------- weight buffer layout (transposed, K-major [N][K]) ------
#define WB_L1   0                         // lin1: [256][128]
#define WB_LYR  32768                     // layers: 8 x [256][512]  (W' = beta*W + omb*I)
#define WB_L2   (32768 + 8 * 131072)      // lin2: [128][256]
#define WB_TOT  (WB_L2 + 32768)

// ------------------------- static device scratch -------------------------
__device__ float  g_dis[NN];
__device__ int    g_rowptr[NN + 1];
__device__ int    g_cnt[NN];
__device__ int    g_bsum[64];
__device__ int    g_boff[64];
__device__ int2   g_ew[NE];                          // packed (src, w-as-int)
__device__ __half g_hh[(size_t)NN * D_HID];          // fp16 h (raw GEMM out; x0 after lin1)
__device__ __half g_Af[(size_t)NN * 512];            // fp16 A: 0..255 t (or h_norm); 256..511 0.5*x0
__device__ __half g_xinf[(size_t)NN * D_IN];         // fp16 input x
__device__ __half g_Wf[WB_TOT];                      // fp16 weights (single precision pass)
__device__ double g_accA[2][2];                      // [parity][sum, sumsq]

// ------------------------- helpers -------------------------
__device__ __forceinline__ uint32_t smem_u32(const void* p) {
    uint32_t a;
    asm("{ .reg .u64 t; cvta.to.shared.u64 t, %1; cvt.u32.u64 %0, t; }" : "=r"(a) : "l"(p));
    return a;
}
__device__ __forceinline__ void cp16(uint32_t dst, const void* src) {
    asm volatile("cp.async.cg.shared.global [%0], [%1], 16;" :: "r"(dst), "l"(src));
}
#define CP_COMMIT() asm volatile("cp.async.commit_group;" ::: "memory")
#define CP_WAIT1()  asm volatile("cp.async.wait_group 1;" ::: "memory")

__device__ __forceinline__ void ldm_x4(uint32_t* r, uint32_t addr) {
    asm volatile("ldmatrix.sync.aligned.m8n8.x4.shared.b16 {%0,%1,%2,%3}, [%4];"
                 : "=r"(r[0]), "=r"(r[1]), "=r"(r[2]), "=r"(r[3]) : "r"(addr));
}
__device__ __forceinline__ void mma16816h(float* c, const uint32_t* a, const uint32_t* b) {
    asm volatile("mma.sync.aligned.m16n8k16.row.col.f32.f16.f16.f32 "
                 "{%0,%1,%2,%3}, {%4,%5,%6,%7}, {%8,%9}, {%0,%1,%2,%3};"
                 : "+f"(c[0]), "+f"(c[1]), "+f"(c[2]), "+f"(c[3])
                 : "r"(a[0]), "r"(a[1]), "r"(a[2]), "r"(a[3]), "r"(b[0]), "r"(b[1]));
}

// ------------------------- setup kernels -------------------------
__global__ void k_zero() {
    int i = blockIdx.x * blockDim.x + threadIdx.x;
    if (i < NN) g_cnt[i] = 0;
}
__global__ void k_count(const int* __restrict__ ei) {
    int e = blockIdx.x * blockDim.x + threadIdx.x;
    if (e < NE) atomicAdd(&g_cnt[ei[NE + e]], 1);
}
__device__ __forceinline__ int block_scan_inc(int v, int* wsum) {
    int lane = threadIdx.x & 31, wid = threadIdx.x >> 5;
#pragma unroll
    for (int o = 1; o < 32; o <<= 1) { int t = __shfl_up_sync(~0u, v, o); if (lane >= o) v += t; }
    if (lane == 31) wsum[wid] = v;
    __syncthreads();
    if (wid == 0) {
        int w = wsum[lane];
#pragma unroll
        for (int o = 1; o < 32; o <<= 1) { int t = __shfl_up_sync(~0u, w, o); if (lane >= o) w += t; }
        wsum[lane] = w;
    }
    __syncthreads();
    return v + (wid > 0 ? wsum[wid - 1] : 0);
}
__global__ void k_scan_part() {
    __shared__ int wsum[32];
    int i = blockIdx.x * 1024 + threadIdx.x;
    int v = (i < NN) ? g_cnt[i] : 0;
    int inc = block_scan_inc(v, wsum);
    if (threadIdx.x == 1023) g_bsum[blockIdx.x] = inc;
}
__global__ void k_scan_top() {
    int lane = threadIdx.x;
    int v0 = (lane < 49) ? g_bsum[lane] : 0;
    int v1 = (lane + 32 < 49) ? g_bsum[lane + 32] : 0;
    int s0 = v0;
#pragma unroll
    for (int o = 1; o < 32; o <<= 1) { int t = __shfl_up_sync(~0u, s0, o); if (lane >= o) s0 += t; }
    int tot0 = __shfl_sync(~0u, s0, 31);
    int s1 = v1;
#pragma unroll
    for (int o = 1; o < 32; o <<= 1) { int t = __shfl_up_sync(~0u, s1, o); if (lane >= o) s1 += t; }
    int tot1 = __shfl_sync(~0u, s1, 31);
    g_boff[lane] = s0 - v0;
    if (lane + 32 < 49) g_boff[lane + 32] = tot0 + s1 - v1;
    if (lane == 0) g_rowptr[NN] = tot0 + tot1;
}
__global__ void k_scan_out() {
    __shared__ int wsum[32];
    int i = blockIdx.x * 1024 + threadIdx.x;
    int v = (i < NN) ? g_cnt[i] : 0;
    int inc = block_scan_inc(v, wsum);
    if (i < NN) {
        int rp = g_boff[blockIdx.x] + inc - v;
        g_rowptr[i] = rp;
        g_cnt[i] = rp;
        g_dis[i] = rsqrtf((float)(v + 1));
    }
}
__global__ void k_scatter(const int* __restrict__ ei) {
    int e = blockIdx.x * blockDim.x + threadIdx.x;
    if (e < NE) {
        int r = ei[e];
        int c = ei[NE + e];
        int s = atomicAdd(&g_cnt[c], 1);
        g_ew[s] = make_int2(r, __float_as_int(g_dis[r] * g_dis[c]));
    }
}

// ------------------------- fused weight + input prep (fp16) --------------
__global__ void k_prep_wx(const float* __restrict__ lin1_w, const float* __restrict__ w1,
                          const float* __restrict__ w2, const float* __restrict__ lin2_w,
                          const float* __restrict__ x) {
    int idx = blockIdx.x * blockDim.x + threadIdx.x;
    if (idx < WB_TOT) {
        float v;
        if (idx < WB_LYR) {
            int n = idx >> 7, k = idx & 127;
            v = lin1_w[k * 256 + n];
        } else if (idx < WB_L2) {
            int r = idx - WB_LYR;
            int l = r >> 17;
            int q = r & 131071;
            int n = q >> 9, k = q & 511;
            float beta = logf((float)(l + 2) / (float)(l + 1));
            float omb = 1.0f - beta;
            if (k < 256) v = beta * w1[l * 65536 + k * 256 + n] + ((k == n) ? omb : 0.0f);
            else {
                int k2 = k - 256;
                v = beta * w2[l * 65536 + k2 * 256 + n] + ((k2 == n) ? omb : 0.0f);
            }
        } else {
            int r = idx - WB_L2;
            int n = r >> 8, k = r & 255;
            v = lin2_w[k * 128 + n];
        }
        g_Wf[idx] = __float2half_rn(v);
    } else {
        size_t xi = (size_t)idx - WB_TOT;
        if (xi < (size_t)NN * D_IN) g_xinf[xi] = __float2half_rn(x[xi]);
    }
}

// ------------------------- SpMM (fp16 gather, fused norm+relu) -----------
// R13 form (proven best): per-warp node, unroll-4, int2 edges, 8 cols/lane.
__global__ void __launch_bounds__(64, 24) k_spmm(int l, const float* __restrict__ gam,
                                                 const float* __restrict__ bet) {
    int par = l & 1;
    if (blockIdx.x == 0 && threadIdx.x == 0) { g_accA[par][0] = 0.0; g_accA[par][1] = 0.0; }
    int warp = blockIdx.x * 2 + (threadIdx.x >> 5);
    int lane = threadIdx.x & 31;
    if (warp >= NN) return;

    float ca[8], cb[8];
    if (l == 0) {
#pragma unroll
        for (int j = 0; j < 8; j++) { ca[j] = 1.0f; cb[j] = 0.0f; }
    } else {
        int pp = (l - 1) & 1;
        double cnt = (double)NN * (double)D_HID;
        double mu = g_accA[pp][0] / cnt;
        double var = g_accA[pp][1] / cnt - mu * mu;
        if (var < 0.0) var = 0.0;
        float inv = (float)(1.0 / (sqrt(var) + 1e-5));
        float muf = (float)mu;
        int c0 = lane * 8;
        float4 ga = *(const float4*)(gam + c0);
        float4 gb = *(const float4*)(gam + c0 + 4);
        float4 ba = *(const float4*)(bet + c0);
        float4 bb = *(const float4*)(bet + c0 + 4);
        float gv[8] = {ga.x, ga.y, ga.z, ga.w, gb.x, gb.y, gb.z, gb.w};
        float bv[8] = {ba.x, ba.y, ba.z, ba.w, bb.x, bb.y, bb.z, bb.w};
#pragma unroll
        for (int j = 0; j < 8; j++) { ca[j] = gv[j] * inv; cb[j] = bv[j] - muf * ca[j]; }
    }

    int c = warp;
    float dc = g_dis[c];
    float wself = dc * dc;
    float acc[8];
    {
        uint4 q = __ldg((const uint4*)(g_hh + (size_t)c * D_HID + lane * 8));
        float2 f0 = __half22float2(*(__half2*)&q.x);
        float2 f1 = __half22float2(*(__half2*)&q.y);
        float2 f2 = __half22float2(*(__half2*)&q.z);
        float2 f3 = __half22float2(*(__half2*)&q.w);
        float v[8] = {f0.x, f0.y, f1.x, f1.y, f2.x, f2.y, f3.x, f3.y};
#pragma unroll
        for (int j = 0; j < 8; j++) acc[j] = wself * fmaxf(ca[j] * v[j] + cb[j], 0.0f);
    }

    int beg = g_rowptr[c], end = g_rowptr[c + 1];
#pragma unroll 4
    for (int e = beg; e < end; e++) {
        int2 ew = __ldg(&g_ew[e]);
        int   s = ew.x;
        float w = __int_as_float(ew.y);
        uint4 q = __ldg((const uint4*)(g_hh + (size_t)s * D_HID + lane * 8));
        float2 f0 = __half22float2(*(__half2*)&q.x);
        float2 f1 = __half22float2(*(__half2*)&q.y);
        float2 f2 = __half22float2(*(__half2*)&q.z);
        float2 f3 = __half22float2(*(__half2*)&q.w);
        float v[8] = {f0.x, f0.y, f1.x, f1.y, f2.x, f2.y, f3.x, f3.y};
#pragma unroll
        for (int j = 0; j < 8; j++) acc[j] += w * fmaxf(ca[j] * v[j] + cb[j], 0.0f);
    }

    __half2 o[4];
#pragma unroll
    for (int j = 0; j < 4; j++)
        o[j] = __floats2half2_rn(0.5f * acc[2 * j], 0.5f * acc[2 * j + 1]);
    *(uint4*)(g_Af + (size_t)c * 512 + lane * 8) = *(uint4*)o;
}

// ------------------------- fp16 1-pass GEMM (8 warps, 2-stage, 2 CTA/SM) -
// stage: A fp16 (10240B) | B fp16 (10240B)
// mode 1: lin1   A=g_xinf (lda=128), K=128 : relu(acc+bias)->g_hh + 0.5x0 fp16
// mode 2: layer  A=g_Af   (lda=512), K=512 : acc -> g_hh + fp32 stats
// mode 3: lin2   A=g_Af   (lda=512), K=256 : relu(acc+bias)->Cout
#define STG_SZ 20480
#define SM_TOTAL (2 * STG_SZ)

__global__ void __launch_bounds__(256, 2) k_mma(int mode, int bOff, int K, int ldb, int N,
                                                const float* __restrict__ bias,
                                                float* __restrict__ Cout, int parity) {
    extern __shared__ char smem[];
    uint32_t sb = smem_u32(smem);
    int tid = threadIdx.x;
    int lane = tid & 31, wrp = tid >> 5;
    int wm = wrp & 1, wn = wrp >> 1;
    int m0 = blockIdx.y * 128, n0 = blockIdx.x * 128;

    const __half* A = (mode == 1) ? g_xinf : g_Af;
    const int lda = (mode == 1) ? 128 : 512;
    const __half* B = g_Wf + bOff;

    const int nch = K / 32;

    int r0i = tid >> 2, seg0 = (tid & 3);
    int r1i = (tid + 256) >> 2;

    auto load_stage = [&](int s, int ch) {
        int kb = ch * 32;
        uint32_t base = sb + s * STG_SZ;
        int gr0 = m0 + r0i; if (gr0 >= NN) gr0 = 0;
        int gr1 = m0 + r1i; if (gr1 >= NN) gr1 = 0;
        uint32_t d0 = base + r0i * 80 + seg0 * 16;
        uint32_t d1 = base + r1i * 80 + seg0 * 16;
        cp16(d0, A + (size_t)gr0 * lda + kb + seg0 * 8);
        cp16(d1, A + (size_t)gr1 * lda + kb + seg0 * 8);
        cp16(d0 + 10240, B + (size_t)(n0 + r0i) * ldb + kb + seg0 * 8);
        cp16(d1 + 10240, B + (size_t)(n0 + r1i) * ldb + kb + seg0 * 8);
    };

    float acc[4][4][4];
#pragma unroll
    for (int i = 0; i < 4; i++)
#pragma unroll
        for (int j = 0; j < 4; j++)
#pragma unroll
            for (int p = 0; p < 4; p++) acc[i][j][p] = 0.0f;

    load_stage(0, 0); CP_COMMIT();
    load_stage(1, 1); CP_COMMIT();

    int a_row = wm * 64 + (lane & 7) + ((lane >> 3) & 1) * 8;
    int a_colh = (lane >> 4) * 8;
    int b_row2 = wn * 32 + ((lane >> 4) & 1) * 8 + (lane & 7);
    int b_colh = ((lane >> 3) & 1) * 8;

    for (int ch = 0; ch < nch; ch++) {
        int st = ch & 1;
        CP_WAIT1();
        __syncthreads();
        uint32_t base = sb + st * STG_SZ;
#pragma unroll
        for (int k16 = 0; k16 < 2; k16++) {
            uint32_t ah[4][4], bh[4][2];
#pragma unroll
            for (int mt = 0; mt < 4; mt++) {
                uint32_t ad = base + (a_row + mt * 16) * 80 + (k16 * 16 + a_colh) * 2;
                ldm_x4(ah[mt], ad);
            }
#pragma unroll
            for (int np = 0; np < 2; np++) {
                uint32_t bd = base + 10240 + (b_row2 + np * 16) * 80 + (k16 * 16 + b_colh) * 2;
                uint32_t r4[4];
                ldm_x4(r4, bd);
                bh[np * 2][0] = r4[0]; bh[np * 2][1] = r4[1];
                bh[np * 2 + 1][0] = r4[2]; bh[np * 2 + 1][1] = r4[3];
            }
#pragma unroll
            for (int mt = 0; mt < 4; mt++)
#pragma unroll
                for (int nt = 0; nt < 4; nt++)
                    mma16816h(acc[mt][nt], ah[mt], bh[nt]);
        }
        __syncthreads();
        if (ch + 2 < nch) load_stage(st, ch + 2);
        CP_COMMIT();
    }

    // ------------- epilogue -------------
    float sum = 0.0f, ssum = 0.0f;
    int rbase = m0 + wm * 64 + (lane >> 2);
    int cbase = n0 + wn * 32 + (lane & 3) * 2;
#pragma unroll
    for (int mt = 0; mt < 4; mt++) {
#pragma unroll
        for (int half = 0; half < 2; half++) {
            int row = rbase + mt * 16 + half * 8;
            if (row >= NN) continue;
#pragma unroll
            for (int nt = 0; nt < 4; nt++) {
                int c = cbase + nt * 8;
                float v0 = acc[mt][nt][half * 2 + 0];
                float v1 = acc[mt][nt][half * 2 + 1];
                if (mode == 2) {
                    *(__half2*)(g_hh + (size_t)row * 256 + c) = __floats2half2_rn(v0, v1);
                    sum += v0 + v1;
                    ssum += v0 * v0 + v1 * v1;
                } else if (mode == 1) {
                    float r0 = fmaxf(v0 + __ldg(&bias[c]), 0.0f);
                    float r1 = fmaxf(v1 + __ldg(&bias[c + 1]), 0.0f);
                    *(__half2*)(g_hh + (size_t)row * 256 + c) = __floats2half2_rn(r0, r1);
                    *(__half2*)(g_Af + (size_t)row * 512 + 256 + c) =
                        __floats2half2_rn(0.5f * r0, 0.5f * r1);
                } else {
                    float r0 = fmaxf(v0 + __ldg(&bias[c]), 0.0f);
                    float r1 = fmaxf(v1 + __ldg(&bias[c + 1]), 0.0f);
                    *(float2*)(Cout + (size_t)row * N + c) = make_float2(r0, r1);
                }
            }
        }
    }
    if (mode == 2) {
#pragma unroll
        for (int off = 16; off > 0; off >>= 1) {
            sum  += __shfl_down_sync(0xffffffffu, sum, off);
            ssum += __shfl_down_sync(0xffffffffu, ssum, off);
        }
        __syncthreads();
        float* rs  = (float*)smem;
        float* rss = (float*)smem + 32;
        if (lane == 0) { rs[wrp] = sum; rss[wrp] = ssum; }
        __syncthreads();
        if (tid == 0) {
            float S = 0.f, SS = 0.f;
            for (int w = 0; w < 8; w++) { S += rs[w]; SS += rss[w]; }
            atomicAdd(&g_accA[parity][0], (double)S);
            atomicAdd(&g_accA[parity][1], (double)SS);
        }
    }
}

// ------------------------- final norm -> lin2 input (fp16) ---------------
__global__ void k_norm_final(const float* __restrict__ gam, const float* __restrict__ bet) {
    double cnt = (double)NN * (double)D_HID;
    double mu = g_accA[1][0] / cnt;
    double var = g_accA[1][1] / cnt - mu * mu;
    if (var < 0.0) var = 0.0;
    float inv = (float)(1.0 / (sqrt(var) + 1e-5));
    float muf = (float)mu;
    size_t total = (size_t)NN * D_HID / 4;
    size_t i = (size_t)blockIdx.x * blockDim.x + threadIdx.x;
    if (i >= total) return;
    uint2 q = *(const uint2*)(g_hh + i * 4);
    float2 f0 = __half22float2(*(__half2*)&q.x);
    float2 f1 = __half22float2(*(__half2*)&q.y);
    int c = (int)((i * 4) & (D_HID - 1));
    float4 gg = *(const float4*)(gam + c);
    float4 bb = *(const float4*)(bet + c);
    float r0 = fmaxf(gg.x * ((f0.x - muf) * inv) + bb.x, 0.0f);
    float r1 = fmaxf(gg.y * ((f0.y - muf) * inv) + bb.y, 0.0f);
    float r2 = fmaxf(gg.z * ((f1.x - muf) * inv) + bb.z, 0.0f);
    float r3 = fmaxf(gg.w * ((f1.y - muf) * inv) + bb.w, 0.0f);
    size_t row = (i * 4) >> 8;
    size_t base = row * 512 + c;
    *(__half2*)(g_Af + base)     = __floats2half2_rn(r0, r1);
    *(__half2*)(g_Af + base + 2) = __floats2half2_rn(r2, r3);
}

// ------------------------- launch -------------------------
extern "C" void kernel_launch(void* const* d_in, const int* in_sizes, int n_in,
                              void* d_out, int out_size) {
    const float* x       = (const float*)d_in[0];
    const int*   ei      = (const int*)  d_in[1];
    const float* lin1_w  = (const float*)d_in[2];
    const float* lin1_b  = (const float*)d_in[3];
    const float* conv_w1 = (const float*)d_in[4];
    const float* conv_w2 = (const float*)d_in[5];
    const float* gamma   = (const float*)d_in[6];
    const float* betaa   = (const float*)d_in[7];
    const float* lin2_w  = (const float*)d_in[8];
    const float* lin2_b  = (const float*)d_in[9];
    float* out = (float*)d_out;

    static int smem_set = 0;
    if (!smem_set) {
        cudaFuncSetAttribute(k_mma, cudaFuncAttributeMaxDynamicSharedMemorySize, SM_TOTAL);
        smem_set = 1;
    }

    const int MT = (NN + 127) / 128;  // 391
    const int PREP_N = WB_TOT + NN * D_IN;

    k_prep_wx<<<(PREP_N + 255) / 256, 256>>>(lin1_w, conv_w1, conv_w2, lin2_w, x);
    k_zero<<<(NN + 255) / 256, 256>>>();
    k_count<<<(NE + 255) / 256, 256>>>(ei);
    k_mma<<<dim3(2, MT), 256, SM_TOTAL>>>(1, WB_L1, 128, 128, 256, lin1_b, nullptr, 0);
    k_scan_part<<<49, 1024>>>();
    k_scan_top<<<1, 32>>>();
    k_scan_out<<<49, 1024>>>();
    k_scatter<<<(NE + 255) / 256, 256>>>(ei);

    for (int l = 0; l < NL; l++) {
        k_spmm<<<(NN + 1) / 2, 64>>>(l, gamma + (size_t)(l > 0 ? l - 1 : 0) * D_HID,
                                     betaa + (size_t)(l > 0 ? l - 1 : 0) * D_HID);
        k_mma<<<dim3(2, MT), 256, SM_TOTAL>>>(2, WB_LYR + l * 131072, 512, 512, 256,
                                              nullptr, nullptr, l & 1);
    }

    k_norm_final<<<(NN * D_HID / 4 + 255) / 256, 256>>>(gamma + 7 * (size_t)D_HID,
                                                        betaa + 7 * (size_t)D_HID);

    k_mma<<<dim3(1, MT), 256, SM_TOTAL>>>(3, WB_L2, 256, 256, 128, lin2_b, out, 0);

    (void)in_sizes; (void)n_in; (void)out_size;
}